// round 1
// baseline (speedup 1.0000x reference)
#include <cuda_runtime.h>
#include <cuda_bf16.h>

#define N_POINTS   262144
#define NUM_CLASSES 20
#define K_NEIGHBORS 16

// 20 floats per row = 5 float4 (80 bytes, 16B-aligned per row)
__device__ float4 g_probs[N_POINTS * 5];
__device__ double g_sum;
__device__ unsigned long long g_count;
__device__ int g_is64;   // 1 if labels/reference_index are int64, 0 if int32

// ---------------------------------------------------------------------------
// Kernel 0: zero accumulators + detect index dtype.
// reference_index values are in [0, N). If the buffer is int32 but we read
// int64, the high word of almost every sample is a random index != 0, giving
// a value >= 2^32 -> out of range -> detected. Deterministic for fixed input.
// ---------------------------------------------------------------------------
__global__ void lac_init_kernel(const void* __restrict__ ref_raw) {
    __shared__ int bad;
    int tid = threadIdx.x;
    if (tid == 0) { g_sum = 0.0; g_count = 0ULL; bad = 0; }
    __syncthreads();
    const long long* p = (const long long*)ref_raw;
    // 2048 int64 samples = 16KB, far within the >=16MB index buffer.
    for (int i = tid; i < 2048; i += blockDim.x) {
        long long v = p[i];
        if (v < 0 || v >= (long long)N_POINTS) bad = 1;
    }
    __syncthreads();
    if (tid == 0) g_is64 = bad ? 0 : 1;
}

// ---------------------------------------------------------------------------
// Kernel 1: row softmax, one thread per point (20 classes in registers).
// ---------------------------------------------------------------------------
__global__ void lac_softmax_kernel(const float* __restrict__ logits) {
    int i = blockIdx.x * blockDim.x + threadIdx.x;
    if (i >= N_POINTS) return;

    const float4* in = (const float4*)logits + (long long)i * 5;
    float4 v[5];
#pragma unroll
    for (int j = 0; j < 5; j++) v[j] = in[j];
    float* f = (float*)v;

    float m = f[0];
#pragma unroll
    for (int j = 1; j < NUM_CLASSES; j++) m = fmaxf(m, f[j]);
    float s = 0.f;
#pragma unroll
    for (int j = 0; j < NUM_CLASSES; j++) { float e = __expf(f[j] - m); f[j] = e; s += e; }
    float inv = __frcp_rn(s);
#pragma unroll
    for (int j = 0; j < NUM_CLASSES; j++) f[j] *= inv;

#pragma unroll
    for (int j = 0; j < 5; j++) g_probs[(long long)i * 5 + j] = v[j];
}

// ---------------------------------------------------------------------------
// Kernel 2: per-point neighbor loop. Label-gate before loading neighbor probs
// (~1/20 match rate -> 20x less random prob-gather traffic).
// ---------------------------------------------------------------------------
__device__ __forceinline__ long long load_index(const void* p, long long idx, bool is64) {
    return is64 ? ((const long long*)p)[idx] : (long long)((const int*)p)[idx];
}

__global__ void lac_loss_kernel(const void* __restrict__ labels_raw,
                                const void* __restrict__ ref_raw) {
    const bool is64 = (g_is64 != 0);
    int i = blockIdx.x * blockDim.x + threadIdx.x;

    float acc = 0.f;
    int   cnt = 0;

    if (i < N_POINTS) {
        int my_lbl = (int)load_index(labels_raw, i, is64);
        if (my_lbl >= 0) {
            float4 sp[5];
#pragma unroll
            for (int j = 0; j < 5; j++) sp[j] = g_probs[(long long)i * 5 + j];
            const float* s = (const float*)sp;

#pragma unroll
            for (int k = 0; k < K_NEIGHBORS; k++) {
                long long ri = load_index(ref_raw, (long long)i * K_NEIGHBORS + k, is64);
                if (ri < 0) continue;                       // knn_mask
                int idx = (int)ri;
                int nl = (int)load_index(labels_raw, idx, is64);
                if (nl != my_lbl) continue;                 // same_label & neighbor_valid
                float d = 0.f;
#pragma unroll
                for (int j = 0; j < 5; j++) {
                    float4 q = g_probs[(long long)idx * 5 + j];
                    float d0 = s[j * 4 + 0] - q.x;
                    float d1 = s[j * 4 + 1] - q.y;
                    float d2 = s[j * 4 + 2] - q.z;
                    float d3 = s[j * 4 + 3] - q.w;
                    d = fmaf(d0, d0, d); d = fmaf(d1, d1, d);
                    d = fmaf(d2, d2, d); d = fmaf(d3, d3, d);
                }
                acc += d;
                cnt++;
            }
        }
    }

    // block reduction: warp shuffle -> shared -> one atomic per block
#pragma unroll
    for (int o = 16; o > 0; o >>= 1) {
        acc += __shfl_down_sync(0xffffffff, acc, o);
        cnt += __shfl_down_sync(0xffffffff, cnt, o);
    }
    __shared__ float ssum[8];
    __shared__ int   scnt[8];
    int lane = threadIdx.x & 31;
    int w    = threadIdx.x >> 5;
    if (lane == 0) { ssum[w] = acc; scnt[w] = cnt; }
    __syncthreads();
    if (w == 0) {
        acc = (lane < (blockDim.x >> 5)) ? ssum[lane] : 0.f;
        cnt = (lane < (blockDim.x >> 5)) ? scnt[lane] : 0;
#pragma unroll
        for (int o = 4; o > 0; o >>= 1) {
            acc += __shfl_down_sync(0xffffffff, acc, o);
            cnt += __shfl_down_sync(0xffffffff, cnt, o);
        }
        if (lane == 0) {
            atomicAdd(&g_sum, (double)acc);
            atomicAdd(&g_count, (unsigned long long)cnt);
        }
    }
}

// ---------------------------------------------------------------------------
// Kernel 3: finalize scalar
// ---------------------------------------------------------------------------
__global__ void lac_finalize_kernel(float* __restrict__ out) {
    double c = (double)g_count;
    if (c < 1.0) c = 1.0;
    out[0] = (float)(g_sum / c);
}

extern "C" void kernel_launch(void* const* d_in, const int* in_sizes, int n_in,
                              void* d_out, int out_size) {
    const float* seg_logits = (const float*)d_in[0];
    // d_in[1] = coord, unused (KNN indices are given)
    const void* labels = d_in[2];
    const void* ref    = d_in[3];
    float* out = (float*)d_out;

    const int TPB = 256;
    const int blocks = (N_POINTS + TPB - 1) / TPB;

    lac_init_kernel<<<1, 256>>>(ref);
    lac_softmax_kernel<<<blocks, TPB>>>(seg_logits);
    lac_loss_kernel<<<blocks, TPB>>>(labels, ref);
    lac_finalize_kernel<<<1, 1>>>(out);
}

// round 2
// speedup vs baseline: 1.0122x; 1.0122x over previous
#include <cuda_runtime.h>
#include <cuda_bf16.h>

#define N_POINTS    262144
#define NUM_CLASSES 20
#define K_NEIGHBORS 16
#define FULLMASK    0xffffffffu

// 20 floats per row = 5 float4 (80 bytes per row)
__device__ float4 g_probs[N_POINTS * 5];
__device__ signed char g_lab8[N_POINTS];
__device__ double g_sum;
__device__ unsigned long long g_count;
__device__ unsigned int g_done;   // zero-initialized; last block self-resets

// ---------------------------------------------------------------------------
// Per-block index-dtype detection. reference_index values lie in [0, N).
// Read 64 samples as int64: if the buffer is really int32, nearly every
// sample has a nonzero high word -> value >= 2^32 -> detected. Warp ballot.
// Deterministic for fixed input.
// ---------------------------------------------------------------------------
__device__ __forceinline__ bool detect_is64(const void* __restrict__ ref_raw) {
    __shared__ int s_is64;
    if (threadIdx.x < 32) {
        const long long* p = (const long long*)ref_raw;
        long long a = p[threadIdx.x];
        long long b = p[threadIdx.x + 32];
        int bad = (a < 0 || a >= (long long)N_POINTS ||
                   b < 0 || b >= (long long)N_POINTS) ? 1 : 0;
        unsigned m = __ballot_sync(FULLMASK, bad);
        if (threadIdx.x == 0) s_is64 = (m == 0u);
    }
    __syncthreads();
    return s_is64 != 0;
}

// ---------------------------------------------------------------------------
// Pass 1: zero accumulators (block 0), compact labels to int8, row softmax.
// ---------------------------------------------------------------------------
__global__ void lac_pass1(const float* __restrict__ logits,
                          const void* __restrict__ labels_raw,
                          const void* __restrict__ ref_raw) {
    const bool is64 = detect_is64(ref_raw);
    int i = blockIdx.x * blockDim.x + threadIdx.x;
    if (blockIdx.x == 0 && threadIdx.x == 0) { g_sum = 0.0; g_count = 0ULL; }
    if (i >= N_POINTS) return;

    // compact label
    long long lbl = is64 ? ((const long long*)labels_raw)[i]
                         : (long long)((const int*)labels_raw)[i];
    g_lab8[i] = (signed char)lbl;

    // softmax (20 classes in registers)
    const float4* in = (const float4*)logits + (long long)i * 5;
    float4 v[5];
#pragma unroll
    for (int j = 0; j < 5; j++) v[j] = in[j];
    float* f = (float*)v;

    float m = f[0];
#pragma unroll
    for (int j = 1; j < NUM_CLASSES; j++) m = fmaxf(m, f[j]);
    float s = 0.f;
#pragma unroll
    for (int j = 0; j < NUM_CLASSES; j++) { float e = __expf(f[j] - m); f[j] = e; s += e; }
    float inv = __frcp_rn(s);
#pragma unroll
    for (int j = 0; j < NUM_CLASSES; j++) f[j] *= inv;

#pragma unroll
    for (int j = 0; j < 5; j++) g_probs[(long long)i * 5 + j] = v[j];
}

// ---------------------------------------------------------------------------
// Pass 2: neighbor loop with staged loads (indices -> labels -> matches),
// block reduction, single atomic per block, last-block finalize.
// ---------------------------------------------------------------------------
__global__ void lac_pass2(const void* __restrict__ ref_raw,
                          float* __restrict__ out) {
    const bool is64 = detect_is64(ref_raw);
    int i = blockIdx.x * blockDim.x + threadIdx.x;

    float acc = 0.f;
    int   cnt = 0;

    if (i < N_POINTS) {
        int myl = (int)g_lab8[i];

        // Stage 1: all 16 neighbor indices via vector loads (both dtypes)
        int idxv[K_NEIGHBORS];
        if (is64) {
            const int4* base = (const int4*)((const char*)ref_raw + (size_t)i * 128);
#pragma unroll
            for (int m = 0; m < 8; m++) {
                int4 v = base[m];
                idxv[2 * m + 0] = v.x;   // low word carries value; -1 preserved
                idxv[2 * m + 1] = v.z;
            }
        } else {
            const int4* base = (const int4*)((const char*)ref_raw + (size_t)i * 64);
#pragma unroll
            for (int m = 0; m < 4; m++) {
                int4 v = base[m];
                idxv[4 * m + 0] = v.x; idxv[4 * m + 1] = v.y;
                idxv[4 * m + 2] = v.z; idxv[4 * m + 3] = v.w;
            }
        }

        // Stage 2: all 16 neighbor labels unconditionally (deep MLP, 1B, L1-friendly)
        int nl[K_NEIGHBORS];
#pragma unroll
        for (int k = 0; k < K_NEIGHBORS; k++) {
            int safe = max(idxv[k], 0);
            nl[k] = (int)__ldg(&g_lab8[safe]);
        }

        // Stage 3: own probs
        float4 sp[5];
#pragma unroll
        for (int j = 0; j < 5; j++) sp[j] = g_probs[(long long)i * 5 + j];
        const float* s = (const float*)sp;

        // Stage 4: matched-neighbor distance
        if (myl >= 0) {
#pragma unroll
            for (int k = 0; k < K_NEIGHBORS; k++) {
                if (idxv[k] >= 0 && nl[k] == myl) {
                    float d = 0.f;
#pragma unroll
                    for (int j = 0; j < 5; j++) {
                        float4 q = g_probs[(long long)idxv[k] * 5 + j];
                        float d0 = s[j * 4 + 0] - q.x;
                        float d1 = s[j * 4 + 1] - q.y;
                        float d2 = s[j * 4 + 2] - q.z;
                        float d3 = s[j * 4 + 3] - q.w;
                        d = fmaf(d0, d0, d); d = fmaf(d1, d1, d);
                        d = fmaf(d2, d2, d); d = fmaf(d3, d3, d);
                    }
                    acc += d;
                    cnt++;
                }
            }
        }
    }

    // block reduction: warp shuffle -> shared -> one atomic per block
#pragma unroll
    for (int o = 16; o > 0; o >>= 1) {
        acc += __shfl_down_sync(FULLMASK, acc, o);
        cnt += __shfl_down_sync(FULLMASK, cnt, o);
    }
    __shared__ float ssum[8];
    __shared__ int   scnt[8];
    int lane = threadIdx.x & 31;
    int w    = threadIdx.x >> 5;
    if (lane == 0) { ssum[w] = acc; scnt[w] = cnt; }
    __syncthreads();
    if (w == 0) {
        int nw = blockDim.x >> 5;
        acc = (lane < nw) ? ssum[lane] : 0.f;
        cnt = (lane < nw) ? scnt[lane] : 0;
#pragma unroll
        for (int o = 4; o > 0; o >>= 1) {
            acc += __shfl_down_sync(FULLMASK, acc, o);
            cnt += __shfl_down_sync(FULLMASK, cnt, o);
        }
        if (lane == 0) {
            atomicAdd(&g_sum, (double)acc);
            atomicAdd(&g_count, (unsigned long long)cnt);
            __threadfence();
            unsigned int done = atomicAdd(&g_done, 1u);
            if (done == gridDim.x - 1) {
                double sum = *(volatile double*)&g_sum;
                double c   = (double)*(volatile unsigned long long*)&g_count;
                if (c < 1.0) c = 1.0;
                out[0] = (float)(sum / c);
                g_done = 0;   // self-reset for next graph replay
            }
        }
    }
}

extern "C" void kernel_launch(void* const* d_in, const int* in_sizes, int n_in,
                              void* d_out, int out_size) {
    const float* seg_logits = (const float*)d_in[0];
    // d_in[1] = coord, unused (KNN indices are given)
    const void* labels = d_in[2];
    const void* ref    = d_in[3];
    float* out = (float*)d_out;

    const int TPB = 256;
    const int blocks = (N_POINTS + TPB - 1) / TPB;

    lac_pass1<<<blocks, TPB>>>(seg_logits, labels, ref);
    lac_pass2<<<blocks, TPB>>>(ref, out);
}

// round 3
// speedup vs baseline: 1.0170x; 1.0048x over previous
#include <cuda_runtime.h>
#include <cuda_bf16.h>

#define N_POINTS    262144
#define NUM_CLASSES 20
#define K_NEIGHBORS 16
#define SPLIT       4                 // threads per point in pass 2
#define K_PER       (K_NEIGHBORS / SPLIT)
#define FULLMASK    0xffffffffu

// 20 floats per row = 5 float4 (80 bytes per row)
__device__ float4 g_probs[N_POINTS * 5];
__device__ signed char g_lab8[N_POINTS];
__device__ double g_sum;
__device__ unsigned long long g_count;
__device__ unsigned int g_done;   // zero-initialized; last block self-resets

// ---------------------------------------------------------------------------
// Per-block index-dtype detection. reference_index values lie in [0, N).
// If the buffer is int32 but read as int64, nearly every sample has a nonzero
// high word -> out of range -> detected. Deterministic for fixed input.
// ---------------------------------------------------------------------------
__device__ __forceinline__ bool detect_is64(const void* __restrict__ ref_raw) {
    __shared__ int s_is64;
    if (threadIdx.x < 32) {
        const long long* p = (const long long*)ref_raw;
        long long a = p[threadIdx.x];
        long long b = p[threadIdx.x + 32];
        int bad = (a < 0 || a >= (long long)N_POINTS ||
                   b < 0 || b >= (long long)N_POINTS) ? 1 : 0;
        unsigned m = __ballot_sync(FULLMASK, bad);
        if (threadIdx.x == 0) s_is64 = (m == 0u);
    }
    __syncthreads();
    return s_is64 != 0;
}

// ---------------------------------------------------------------------------
// Pass 1: zero accumulators (block 0), compact labels to int8, row softmax.
// ---------------------------------------------------------------------------
__global__ void lac_pass1(const float* __restrict__ logits,
                          const void* __restrict__ labels_raw,
                          const void* __restrict__ ref_raw) {
    const bool is64 = detect_is64(ref_raw);
    int i = blockIdx.x * blockDim.x + threadIdx.x;
    if (blockIdx.x == 0 && threadIdx.x == 0) { g_sum = 0.0; g_count = 0ULL; }
    if (i >= N_POINTS) return;

    long long lbl = is64 ? ((const long long*)labels_raw)[i]
                         : (long long)((const int*)labels_raw)[i];
    g_lab8[i] = (signed char)lbl;

    const float4* in = (const float4*)logits + (long long)i * 5;
    float4 v[5];
#pragma unroll
    for (int j = 0; j < 5; j++) v[j] = in[j];
    float* f = (float*)v;

    float m = f[0];
#pragma unroll
    for (int j = 1; j < NUM_CLASSES; j++) m = fmaxf(m, f[j]);
    float s = 0.f;
#pragma unroll
    for (int j = 0; j < NUM_CLASSES; j++) { float e = __expf(f[j] - m); f[j] = e; s += e; }
    float inv = __frcp_rn(s);
#pragma unroll
    for (int j = 0; j < NUM_CLASSES; j++) f[j] *= inv;

#pragma unroll
    for (int j = 0; j < 5; j++) g_probs[(long long)i * 5 + j] = v[j];
}

// ---------------------------------------------------------------------------
// Pass 2: SPLIT threads per point, K_PER neighbors each. Staged loads for
// deep MLP, label-gate on the expensive prob gather, block reduction,
// single atomic per block, last-block finalize.
// ---------------------------------------------------------------------------
__global__ void __launch_bounds__(256)
lac_pass2(const void* __restrict__ ref_raw, float* __restrict__ out) {
    const bool is64 = detect_is64(ref_raw);
    long long t = (long long)blockIdx.x * blockDim.x + threadIdx.x;
    int i = (int)(t >> 2);          // point index (SPLIT = 4)
    int h = (int)(t & (SPLIT - 1)); // which quarter of the neighbor list

    float acc = 0.f;
    int   cnt = 0;

    {
        // Stage 1: this thread's K_PER=4 neighbor indices (coalesced vectors)
        int idxv[K_PER];
        if (is64) {
            // 4 int64 = 32 B = two int4 loads
            const int4* base = (const int4*)((const char*)ref_raw +
                                ((size_t)i * K_NEIGHBORS + (size_t)h * K_PER) * 8);
            int4 v0 = base[0];
            int4 v1 = base[1];
            idxv[0] = v0.x; idxv[1] = v0.z;   // low words; -1 preserved
            idxv[2] = v1.x; idxv[3] = v1.z;
        } else {
            const int4* base = (const int4*)((const char*)ref_raw +
                                ((size_t)i * K_NEIGHBORS + (size_t)h * K_PER) * 4);
            int4 v0 = base[0];
            idxv[0] = v0.x; idxv[1] = v0.y; idxv[2] = v0.z; idxv[3] = v0.w;
        }

        // Stage 2: all 4 neighbor labels unconditionally (deep MLP, 1B each)
        int nl[K_PER];
#pragma unroll
        for (int k = 0; k < K_PER; k++) {
            int safe = max(idxv[k], 0);
            nl[k] = (int)__ldg(&g_lab8[safe]);
        }

        int myl = (int)g_lab8[i];   // 4 sibling lanes same addr -> broadcast

        // Stage 3: own probs (sibling lanes broadcast, no extra traffic)
        float4 sp[5];
#pragma unroll
        for (int j = 0; j < 5; j++) sp[j] = g_probs[(long long)i * 5 + j];
        const float* s = (const float*)sp;

        // Stage 4: matched-neighbor distances
        if (myl >= 0) {
#pragma unroll
            for (int k = 0; k < K_PER; k++) {
                if (idxv[k] >= 0 && nl[k] == myl) {
                    float d = 0.f;
#pragma unroll
                    for (int j = 0; j < 5; j++) {
                        float4 q = g_probs[(long long)idxv[k] * 5 + j];
                        float d0 = s[j * 4 + 0] - q.x;
                        float d1 = s[j * 4 + 1] - q.y;
                        float d2 = s[j * 4 + 2] - q.z;
                        float d3 = s[j * 4 + 3] - q.w;
                        d = fmaf(d0, d0, d); d = fmaf(d1, d1, d);
                        d = fmaf(d2, d2, d); d = fmaf(d3, d3, d);
                    }
                    acc += d;
                    cnt++;
                }
            }
        }
    }

    // block reduction: warp shuffle -> shared -> one atomic per block
#pragma unroll
    for (int o = 16; o > 0; o >>= 1) {
        acc += __shfl_down_sync(FULLMASK, acc, o);
        cnt += __shfl_down_sync(FULLMASK, cnt, o);
    }
    __shared__ float ssum[8];
    __shared__ int   scnt[8];
    int lane = threadIdx.x & 31;
    int w    = threadIdx.x >> 5;
    if (lane == 0) { ssum[w] = acc; scnt[w] = cnt; }
    __syncthreads();
    if (w == 0) {
        int nw = blockDim.x >> 5;
        acc = (lane < nw) ? ssum[lane] : 0.f;
        cnt = (lane < nw) ? scnt[lane] : 0;
#pragma unroll
        for (int o = 4; o > 0; o >>= 1) {
            acc += __shfl_down_sync(FULLMASK, acc, o);
            cnt += __shfl_down_sync(FULLMASK, cnt, o);
        }
        if (lane == 0) {
            atomicAdd(&g_sum, (double)acc);
            atomicAdd(&g_count, (unsigned long long)cnt);
            __threadfence();
            unsigned int done = atomicAdd(&g_done, 1u);
            if (done == gridDim.x - 1) {
                double sum = *(volatile double*)&g_sum;
                double c   = (double)*(volatile unsigned long long*)&g_count;
                if (c < 1.0) c = 1.0;
                out[0] = (float)(sum / c);
                g_done = 0;   // self-reset for next graph replay
            }
        }
    }
}

extern "C" void kernel_launch(void* const* d_in, const int* in_sizes, int n_in,
                              void* d_out, int out_size) {
    const float* seg_logits = (const float*)d_in[0];
    // d_in[1] = coord, unused (KNN indices are given)
    const void* labels = d_in[2];
    const void* ref    = d_in[3];
    float* out = (float*)d_out;

    const int TPB = 256;
    const int blocks1 = (N_POINTS + TPB - 1) / TPB;               // 1024
    const int blocks2 = (N_POINTS * SPLIT + TPB - 1) / TPB;       // 4096

    lac_pass1<<<blocks1, TPB>>>(seg_logits, labels, ref);
    lac_pass2<<<blocks2, TPB>>>(ref, out);
}

// round 4
// speedup vs baseline: 1.6404x; 1.6129x over previous
#include <cuda_runtime.h>
#include <cuda_bf16.h>

#define N_POINTS    262144
#define NUM_CLASSES 20
#define K_NEIGHBORS 16
#define FULLMASK    0xffffffffu

// packed labels: 5 bits each, 6 per uint32
#define NWORDS      43691            // ceil(262144 / 6)
#define NWORDS_PAD  43692            // multiple of 4 for uint4 copies
#define SMEM_BYTES  (NWORDS_PAD * 4) // 174768 B

// probs stored as 5 transposed float4 planes: plane j at [j*N + i]
__device__ float4 g_probs[5 * N_POINTS];
__device__ unsigned g_packed[NWORDS_PAD];
__device__ double g_sum;
__device__ unsigned long long g_count;
__device__ unsigned int g_done;

// ---------------------------------------------------------------------------
// Index-dtype detection (values lie in [0,N); int32 read as int64 -> OOB).
// ---------------------------------------------------------------------------
__device__ __forceinline__ bool detect_is64(const void* __restrict__ ref_raw) {
    __shared__ int s_is64;
    if (threadIdx.x < 32) {
        const long long* p = (const long long*)ref_raw;
        long long a = p[threadIdx.x];
        long long b = p[threadIdx.x + 32];
        int bad = (a < 0 || a >= (long long)N_POINTS ||
                   b < 0 || b >= (long long)N_POINTS) ? 1 : 0;
        unsigned m = __ballot_sync(FULLMASK, bad);
        if (threadIdx.x == 0) s_is64 = (m == 0u);
    }
    __syncthreads();
    return s_is64 != 0;
}

// label extract from packed table: q = i/6 via reciprocal, r = i%6
__device__ __forceinline__ int lab_extract(const unsigned* __restrict__ tab, int i) {
    unsigned q = __umulhi((unsigned)i, 715827883u);   // floor(i/6) exact for i<2^18
    unsigned r = (unsigned)i - q * 6u;
    return (int)((tab[q] >> (r * 5u)) & 31u);
}

// ---------------------------------------------------------------------------
// Pass 1: zero accumulators, pack labels (5-bit), row softmax into planes.
// ---------------------------------------------------------------------------
__global__ void lac_pass1(const float* __restrict__ logits,
                          const void* __restrict__ labels_raw,
                          const void* __restrict__ ref_raw) {
    const bool is64 = detect_is64(ref_raw);
    int i = blockIdx.x * blockDim.x + threadIdx.x;
    if (blockIdx.x == 0 && threadIdx.x == 0) { g_sum = 0.0; g_count = 0ULL; }

    // pack 6 labels into one word (threads [0, NWORDS_PAD) )
    if (i < NWORDS_PAD) {
        unsigned w = 0;
#pragma unroll
        for (int t = 0; t < 6; t++) {
            int p = i * 6 + t;
            int lbl = 31;   // invalid sentinel
            if (p < N_POINTS) {
                long long v = is64 ? ((const long long*)labels_raw)[p]
                                   : (long long)((const int*)labels_raw)[p];
                lbl = (int)v & 31;   // -1 -> 31 (invalid); 0..19 preserved
            }
            w |= (unsigned)lbl << (t * 5);
        }
        g_packed[i] = w;
    }

    if (i >= N_POINTS) return;

    const float4* in = (const float4*)logits + (long long)i * 5;
    float4 v[5];
#pragma unroll
    for (int j = 0; j < 5; j++) v[j] = in[j];
    float* f = (float*)v;

    float m = f[0];
#pragma unroll
    for (int j = 1; j < NUM_CLASSES; j++) m = fmaxf(m, f[j]);
    float s = 0.f;
#pragma unroll
    for (int j = 0; j < NUM_CLASSES; j++) { float e = __expf(f[j] - m); f[j] = e; s += e; }
    float inv = __frcp_rn(s);
#pragma unroll
    for (int j = 0; j < NUM_CLASSES; j++) f[j] *= inv;

#pragma unroll
    for (int j = 0; j < 5; j++) g_probs[j * N_POINTS + i] = v[j];   // transposed planes
}

// ---------------------------------------------------------------------------
// Pass 2: persistent blocks; packed label table in shared memory (LDS lookups
// instead of scattered LDG), match-mask gating of prob gathers, block reduce,
// last-block finalize.
// ---------------------------------------------------------------------------
__global__ void __launch_bounds__(1024, 1)
lac_pass2(const void* __restrict__ ref_raw, float* __restrict__ out) {
    extern __shared__ unsigned s_lab[];
    const bool is64 = detect_is64(ref_raw);

    // fill smem label table (uint4 copies)
    {
        const uint4* src = (const uint4*)g_packed;
        uint4* dst = (uint4*)s_lab;
        for (int t = threadIdx.x; t < NWORDS_PAD / 4; t += blockDim.x)
            dst[t] = src[t];
    }
    __syncthreads();

    float acc = 0.f;
    int   cnt = 0;

    const int stride = gridDim.x * blockDim.x;
    for (int i = blockIdx.x * blockDim.x + threadIdx.x; i < N_POINTS; i += stride) {
        int myl = lab_extract(s_lab, i);

        // self probs (coalesced plane loads)
        float4 sp[5];
#pragma unroll
        for (int j = 0; j < 5; j++) sp[j] = g_probs[j * N_POINTS + i];
        const float* s = (const float*)sp;

        if (myl != 31) {
#pragma unroll
            for (int h = 0; h < 2; h++) {     // two halves of 8 neighbors
                int idxv[8];
                if (is64) {
                    const int4* base = (const int4*)((const char*)ref_raw +
                                        (size_t)i * 128 + (size_t)h * 64);
#pragma unroll
                    for (int m2 = 0; m2 < 4; m2++) {
                        int4 v = base[m2];
                        idxv[2 * m2 + 0] = v.x;   // low words; -1 preserved
                        idxv[2 * m2 + 1] = v.z;
                    }
                } else {
                    const int4* base = (const int4*)((const char*)ref_raw +
                                        (size_t)i * 64 + (size_t)h * 32);
#pragma unroll
                    for (int m2 = 0; m2 < 2; m2++) {
                        int4 v = base[m2];
                        idxv[4 * m2 + 0] = v.x; idxv[4 * m2 + 1] = v.y;
                        idxv[4 * m2 + 2] = v.z; idxv[4 * m2 + 3] = v.w;
                    }
                }

                // match mask via LDS label lookups
                unsigned mask = 0;
#pragma unroll
                for (int k = 0; k < 8; k++) {
                    int safe = max(idxv[k], 0);
                    int nl = lab_extract(s_lab, safe);
                    if (idxv[k] >= 0 && nl == myl) mask |= 1u << k;
                }

                // gather probs only for matches
#pragma unroll
                for (int k = 0; k < 8; k++) {
                    if (mask & (1u << k)) {
                        int idx = idxv[k];
                        float d = 0.f;
#pragma unroll
                        for (int j = 0; j < 5; j++) {
                            float4 q = g_probs[j * N_POINTS + idx];
                            float d0 = s[j * 4 + 0] - q.x;
                            float d1 = s[j * 4 + 1] - q.y;
                            float d2 = s[j * 4 + 2] - q.z;
                            float d3 = s[j * 4 + 3] - q.w;
                            d = fmaf(d0, d0, d); d = fmaf(d1, d1, d);
                            d = fmaf(d2, d2, d); d = fmaf(d3, d3, d);
                        }
                        acc += d;
                        cnt++;
                    }
                }
            }
        }
    }

    // block reduction (32 warps) -> one atomic per block -> last-block finalize
#pragma unroll
    for (int o = 16; o > 0; o >>= 1) {
        acc += __shfl_down_sync(FULLMASK, acc, o);
        cnt += __shfl_down_sync(FULLMASK, cnt, o);
    }
    __shared__ float ssum[32];
    __shared__ int   scnt[32];
    int lane = threadIdx.x & 31;
    int w    = threadIdx.x >> 5;
    if (lane == 0) { ssum[w] = acc; scnt[w] = cnt; }
    __syncthreads();
    if (w == 0) {
        int nw = blockDim.x >> 5;
        acc = (lane < nw) ? ssum[lane] : 0.f;
        cnt = (lane < nw) ? scnt[lane] : 0;
#pragma unroll
        for (int o = 16; o > 0; o >>= 1) {
            acc += __shfl_down_sync(FULLMASK, acc, o);
            cnt += __shfl_down_sync(FULLMASK, cnt, o);
        }
        if (lane == 0) {
            atomicAdd(&g_sum, (double)acc);
            atomicAdd(&g_count, (unsigned long long)cnt);
            __threadfence();
            unsigned int done = atomicAdd(&g_done, 1u);
            if (done == gridDim.x - 1) {
                double sum = *(volatile double*)&g_sum;
                double c   = (double)*(volatile unsigned long long*)&g_count;
                if (c < 1.0) c = 1.0;
                out[0] = (float)(sum / c);
                g_done = 0;   // self-reset for next graph replay
            }
        }
    }
}

extern "C" void kernel_launch(void* const* d_in, const int* in_sizes, int n_in,
                              void* d_out, int out_size) {
    const float* seg_logits = (const float*)d_in[0];
    // d_in[1] = coord, unused
    const void* labels = d_in[2];
    const void* ref    = d_in[3];
    float* out = (float*)d_out;

    cudaFuncSetAttribute(lac_pass2, cudaFuncAttributeMaxDynamicSharedMemorySize,
                         SMEM_BYTES);

    const int TPB1 = 256;
    const int blocks1 = (N_POINTS + TPB1 - 1) / TPB1;   // 1024

    lac_pass1<<<blocks1, TPB1>>>(seg_logits, labels, ref);
    lac_pass2<<<152, 1024, SMEM_BYTES>>>(ref, out);
}

// round 5
// speedup vs baseline: 1.8913x; 1.1530x over previous
#include <cuda_runtime.h>
#include <cuda_bf16.h>

#define N_POINTS    262144
#define NUM_CLASSES 20
#define K_NEIGHBORS 16
#define FULLMASK    0xffffffffu

// packed labels: 5 bits each, 6 per uint32
#define NWORDS      43691            // ceil(262144 / 6)
#define NWORDS_PAD  43692            // multiple of 4 for uint4 copies
#define SMEM_BYTES  (NWORDS_PAD * 4) // 174768 B

#define GRID2       152
#define TPB2        1024
#define N_TASKS     (N_POINTS * 4)   // (point, quarter) tasks, 4 neighbors each

// probs stored as 5 transposed float4 planes: plane j at [j*N + i]
__device__ float4 g_probs[5 * N_POINTS];
__device__ unsigned g_packed[NWORDS_PAD];
__device__ double g_sum;
__device__ unsigned long long g_count;
__device__ unsigned int g_done;

// ---------------------------------------------------------------------------
// Index-dtype detection (values lie in [0,N); int32 read as int64 -> OOB).
// ---------------------------------------------------------------------------
__device__ __forceinline__ bool detect_is64(const void* __restrict__ ref_raw) {
    __shared__ int s_is64;
    if (threadIdx.x < 32) {
        const long long* p = (const long long*)ref_raw;
        long long a = p[threadIdx.x];
        long long b = p[threadIdx.x + 32];
        int bad = (a < 0 || a >= (long long)N_POINTS ||
                   b < 0 || b >= (long long)N_POINTS) ? 1 : 0;
        unsigned m = __ballot_sync(FULLMASK, bad);
        if (threadIdx.x == 0) s_is64 = (m == 0u);
    }
    __syncthreads();
    return s_is64 != 0;
}

// label extract from packed table: q = i/6 via reciprocal, r = i%6
__device__ __forceinline__ int lab_extract(const unsigned* __restrict__ tab, int i) {
    unsigned q = __umulhi((unsigned)i, 715827883u);   // floor(i/6) exact for i<2^18
    unsigned r = (unsigned)i - q * 6u;
    return (int)((tab[q] >> (r * 5u)) & 31u);
}

// ---------------------------------------------------------------------------
// Pass 1: zero accumulators, pack labels (5-bit), row softmax into planes.
// ---------------------------------------------------------------------------
__global__ void lac_pass1(const float* __restrict__ logits,
                          const void* __restrict__ labels_raw,
                          const void* __restrict__ ref_raw) {
    const bool is64 = detect_is64(ref_raw);
    int i = blockIdx.x * blockDim.x + threadIdx.x;
    if (blockIdx.x == 0 && threadIdx.x == 0) { g_sum = 0.0; g_count = 0ULL; }

    if (i < NWORDS_PAD) {
        unsigned w = 0;
#pragma unroll
        for (int t = 0; t < 6; t++) {
            int p = i * 6 + t;
            int lbl = 31;   // invalid sentinel
            if (p < N_POINTS) {
                long long v = is64 ? ((const long long*)labels_raw)[p]
                                   : (long long)((const int*)labels_raw)[p];
                lbl = (int)v & 31;   // -1 -> 31 (invalid); 0..19 preserved
            }
            w |= (unsigned)lbl << (t * 5);
        }
        g_packed[i] = w;
    }

    if (i >= N_POINTS) return;

    const float4* in = (const float4*)logits + (long long)i * 5;
    float4 v[5];
#pragma unroll
    for (int j = 0; j < 5; j++) v[j] = in[j];
    float* f = (float*)v;

    float m = f[0];
#pragma unroll
    for (int j = 1; j < NUM_CLASSES; j++) m = fmaxf(m, f[j]);
    float s = 0.f;
#pragma unroll
    for (int j = 0; j < NUM_CLASSES; j++) { float e = __expf(f[j] - m); f[j] = e; s += e; }
    float inv = __frcp_rn(s);
#pragma unroll
    for (int j = 0; j < NUM_CLASSES; j++) f[j] *= inv;

#pragma unroll
    for (int j = 0; j < 5; j++) g_probs[j * N_POINTS + i] = v[j];   // transposed planes
}

// ---------------------------------------------------------------------------
// Pass 2: persistent blocks; smem label table; (point,quarter) tasks for
// balance + density; ffs-driven matched-gather loop; block reduce; finalize.
// ---------------------------------------------------------------------------
__global__ void __launch_bounds__(TPB2, 1)
lac_pass2(const void* __restrict__ ref_raw, float* __restrict__ out) {
    extern __shared__ unsigned s_lab[];
    const bool is64 = detect_is64(ref_raw);

    {
        const uint4* src = (const uint4*)g_packed;
        uint4* dst = (uint4*)s_lab;
        for (int t = threadIdx.x; t < NWORDS_PAD / 4; t += blockDim.x)
            dst[t] = src[t];
    }
    __syncthreads();

    float acc = 0.f;
    int   cnt = 0;

    const int stride = GRID2 * TPB2;
    for (int task = blockIdx.x * TPB2 + threadIdx.x; task < N_TASKS; task += stride) {
        int i = task >> 2;          // point
        int q = task & 3;           // which 4-neighbor quarter

        // 4 neighbor indices, coalesced (sibling lanes contiguous)
        int idxv[4];
        if (is64) {
            const int4* base = (const int4*)((const char*)ref_raw +
                                (size_t)i * 128 + (size_t)q * 32);
            int4 v0 = base[0];
            int4 v1 = base[1];
            idxv[0] = v0.x; idxv[1] = v0.z;   // low words; -1 preserved
            idxv[2] = v1.x; idxv[3] = v1.z;
        } else {
            const int4* base = (const int4*)((const char*)ref_raw +
                                (size_t)i * 64 + (size_t)q * 16);
            int4 v0 = base[0];
            idxv[0] = v0.x; idxv[1] = v0.y; idxv[2] = v0.z; idxv[3] = v0.w;
        }

        int myl = lab_extract(s_lab, i);   // siblings broadcast

        // match mask from LDS labels
        unsigned mask = 0;
#pragma unroll
        for (int k = 0; k < 4; k++) {
            int safe = max(idxv[k], 0);
            int nl = lab_extract(s_lab, safe);
            if (idxv[k] >= 0 && nl == myl && myl != 31) mask |= 1u << k;
        }

        if (mask) {
            // self probs (coalesced plane loads, siblings share lines)
            float4 sp[5];
#pragma unroll
            for (int j = 0; j < 5; j++) sp[j] = g_probs[j * N_POINTS + i];
            const float* s = (const float*)sp;

            // iterate only over actual matches
            do {
                int k = __ffs(mask) - 1;
                mask &= mask - 1;
                int idx = idxv[k];
                float d = 0.f;
#pragma unroll
                for (int j = 0; j < 5; j++) {
                    float4 qq = g_probs[j * N_POINTS + idx];
                    float d0 = s[j * 4 + 0] - qq.x;
                    float d1 = s[j * 4 + 1] - qq.y;
                    float d2 = s[j * 4 + 2] - qq.z;
                    float d3 = s[j * 4 + 3] - qq.w;
                    d = fmaf(d0, d0, d); d = fmaf(d1, d1, d);
                    d = fmaf(d2, d2, d); d = fmaf(d3, d3, d);
                }
                acc += d;
                cnt++;
            } while (mask);
        }
    }

    // block reduction (32 warps) -> one atomic per block -> last-block finalize
#pragma unroll
    for (int o = 16; o > 0; o >>= 1) {
        acc += __shfl_down_sync(FULLMASK, acc, o);
        cnt += __shfl_down_sync(FULLMASK, cnt, o);
    }
    __shared__ float ssum[32];
    __shared__ int   scnt[32];
    int lane = threadIdx.x & 31;
    int w    = threadIdx.x >> 5;
    if (lane == 0) { ssum[w] = acc; scnt[w] = cnt; }
    __syncthreads();
    if (w == 0) {
        int nw = TPB2 >> 5;
        acc = (lane < nw) ? ssum[lane] : 0.f;
        cnt = (lane < nw) ? scnt[lane] : 0;
#pragma unroll
        for (int o = 16; o > 0; o >>= 1) {
            acc += __shfl_down_sync(FULLMASK, acc, o);
            cnt += __shfl_down_sync(FULLMASK, cnt, o);
        }
        if (lane == 0) {
            atomicAdd(&g_sum, (double)acc);
            atomicAdd(&g_count, (unsigned long long)cnt);
            __threadfence();
            unsigned int done = atomicAdd(&g_done, 1u);
            if (done == gridDim.x - 1) {
                double sum = *(volatile double*)&g_sum;
                double c   = (double)*(volatile unsigned long long*)&g_count;
                if (c < 1.0) c = 1.0;
                out[0] = (float)(sum / c);
                g_done = 0;   // self-reset for next graph replay
            }
        }
    }
}

extern "C" void kernel_launch(void* const* d_in, const int* in_sizes, int n_in,
                              void* d_out, int out_size) {
    const float* seg_logits = (const float*)d_in[0];
    // d_in[1] = coord, unused
    const void* labels = d_in[2];
    const void* ref    = d_in[3];
    float* out = (float*)d_out;

    cudaFuncSetAttribute(lac_pass2, cudaFuncAttributeMaxDynamicSharedMemorySize,
                         SMEM_BYTES);

    const int TPB1 = 256;
    const int blocks1 = (N_POINTS + TPB1 - 1) / TPB1;   // 1024

    lac_pass1<<<blocks1, TPB1>>>(seg_logits, labels, ref);
    lac_pass2<<<GRID2, TPB2, SMEM_BYTES>>>(ref, out);
}

// round 6
// speedup vs baseline: 1.9057x; 1.0076x over previous
#include <cuda_runtime.h>
#include <cuda_bf16.h>

#define N_POINTS    262144
#define NUM_CLASSES 20
#define K_NEIGHBORS 16
#define FULLMASK    0xffffffffu

// packed labels: 5 bits each, 6 per uint32
#define NWORDS      43691            // ceil(262144 / 6)
#define NWORDS_PAD  43692            // multiple of 4 for uint4 copies
#define SMEM_BYTES  (NWORDS_PAD * 4) // 174768 B

#define GRID2       152
#define TPB2        1024
#define N_TASKS     (N_POINTS * 4)   // (point, quarter) tasks, 4 neighbors each

// probs stored as 5 transposed float4 planes: plane j at [j*N + i]
__device__ float4 g_probs[5 * N_POINTS];
__device__ unsigned g_packed[NWORDS_PAD];
__device__ double g_sum;
__device__ unsigned long long g_count;
__device__ unsigned int g_done;

// ---------------------------------------------------------------------------
// Index-dtype detection (values lie in [0,N); int32 read as int64 -> OOB).
// ---------------------------------------------------------------------------
__device__ __forceinline__ bool detect_is64(const void* __restrict__ ref_raw) {
    __shared__ int s_is64;
    if (threadIdx.x < 32) {
        const long long* p = (const long long*)ref_raw;
        long long a = p[threadIdx.x];
        long long b = p[threadIdx.x + 32];
        int bad = (a < 0 || a >= (long long)N_POINTS ||
                   b < 0 || b >= (long long)N_POINTS) ? 1 : 0;
        unsigned m = __ballot_sync(FULLMASK, bad);
        if (threadIdx.x == 0) s_is64 = (m == 0u);
    }
    __syncthreads();
    return s_is64 != 0;
}

// label extract from packed table: q = i/6 via reciprocal, r = i%6
__device__ __forceinline__ int lab_extract(const unsigned* __restrict__ tab, int i) {
    unsigned q = __umulhi((unsigned)i, 715827883u);   // floor(i/6) exact for i<2^18
    unsigned r = (unsigned)i - q * 6u;
    return (int)((tab[q] >> (r * 5u)) & 31u);
}

// load one task's 4 neighbor indices (coalesced, both dtype layouts)
__device__ __forceinline__ void load_idx4(const void* __restrict__ ref_raw,
                                          bool is64, int i, int q, int* idxv) {
    if (is64) {
        const int4* base = (const int4*)((const char*)ref_raw +
                            (size_t)i * 128 + (size_t)q * 32);
        int4 v0 = base[0];
        int4 v1 = base[1];
        idxv[0] = v0.x; idxv[1] = v0.z;   // low words; -1 preserved
        idxv[2] = v1.x; idxv[3] = v1.z;
    } else {
        const int4* base = (const int4*)((const char*)ref_raw +
                            (size_t)i * 64 + (size_t)q * 16);
        int4 v0 = base[0];
        idxv[0] = v0.x; idxv[1] = v0.y; idxv[2] = v0.z; idxv[3] = v0.w;
    }
}

// ---------------------------------------------------------------------------
// Pass 1: zero accumulators, pack labels (5-bit), row softmax into planes.
// ---------------------------------------------------------------------------
__global__ void lac_pass1(const float* __restrict__ logits,
                          const void* __restrict__ labels_raw,
                          const void* __restrict__ ref_raw) {
    const bool is64 = detect_is64(ref_raw);
    int i = blockIdx.x * blockDim.x + threadIdx.x;
    if (blockIdx.x == 0 && threadIdx.x == 0) { g_sum = 0.0; g_count = 0ULL; }

    if (i < NWORDS_PAD) {
        unsigned w = 0;
#pragma unroll
        for (int t = 0; t < 6; t++) {
            int p = i * 6 + t;
            int lbl = 31;   // invalid sentinel
            if (p < N_POINTS) {
                long long v = is64 ? ((const long long*)labels_raw)[p]
                                   : (long long)((const int*)labels_raw)[p];
                lbl = (int)v & 31;   // -1 -> 31 (invalid); 0..19 preserved
            }
            w |= (unsigned)lbl << (t * 5);
        }
        g_packed[i] = w;
    }

    if (i >= N_POINTS) return;

    const float4* in = (const float4*)logits + (long long)i * 5;
    float4 v[5];
#pragma unroll
    for (int j = 0; j < 5; j++) v[j] = in[j];
    float* f = (float*)v;

    float m = f[0];
#pragma unroll
    for (int j = 1; j < NUM_CLASSES; j++) m = fmaxf(m, f[j]);
    float s = 0.f;
#pragma unroll
    for (int j = 0; j < NUM_CLASSES; j++) { float e = __expf(f[j] - m); f[j] = e; s += e; }
    float inv = __frcp_rn(s);
#pragma unroll
    for (int j = 0; j < NUM_CLASSES; j++) f[j] *= inv;

#pragma unroll
    for (int j = 0; j < 5; j++) g_probs[j * N_POINTS + i] = v[j];   // transposed planes
}

// ---------------------------------------------------------------------------
// Pass 2: persistent blocks; smem label table; 2 tasks per thread per
// iteration for ILP; merged 8-bit ffs match loop with lazy self loads.
// ---------------------------------------------------------------------------
__global__ void __launch_bounds__(TPB2, 1)
lac_pass2(const void* __restrict__ ref_raw, float* __restrict__ out) {
    extern __shared__ unsigned s_lab[];
    const bool is64 = detect_is64(ref_raw);

    {
        const uint4* src = (const uint4*)g_packed;
        uint4* dst = (uint4*)s_lab;
        for (int t = threadIdx.x; t < NWORDS_PAD / 4; t += blockDim.x)
            dst[t] = src[t];
    }
    __syncthreads();

    float acc = 0.f;
    int   cnt = 0;

    const int stride = GRID2 * TPB2;
    for (int tA = blockIdx.x * TPB2 + threadIdx.x; tA < N_TASKS; tA += 2 * stride) {
        int tB = tA + stride;
        bool hasB = tB < N_TASKS;

        int iA = tA >> 2, qA = tA & 3;
        int iB = tB >> 2, qB = tB & 3;

        // batched index loads (up to 4 int4 LDGs in flight)
        int idxA[4], idxB[4];
        load_idx4(ref_raw, is64, iA, qA, idxA);
        if (hasB) load_idx4(ref_raw, is64, iB, qB, idxB);
        else { idxB[0] = idxB[1] = idxB[2] = idxB[3] = -1; }

        int mylA = lab_extract(s_lab, iA);
        int mylB = hasB ? lab_extract(s_lab, iB) : 31;

        // merged 8-bit match mask via LDS label lookups
        unsigned mask = 0;
#pragma unroll
        for (int k = 0; k < 4; k++) {
            int sA = max(idxA[k], 0);
            int nlA = lab_extract(s_lab, sA);
            if (idxA[k] >= 0 && nlA == mylA && mylA != 31) mask |= 1u << k;
        }
#pragma unroll
        for (int k = 0; k < 4; k++) {
            int sB = max(idxB[k], 0);
            int nlB = lab_extract(s_lab, sB);
            if (idxB[k] >= 0 && nlB == mylB && mylB != 31) mask |= 1u << (k + 4);
        }

        // iterate only over matches; load self + neighbor rows together
        while (mask) {
            int k = __ffs(mask) - 1;
            mask &= mask - 1;
            bool isA = k < 4;
            int pt = isA ? iA : iB;
            int nb = isA ? idxA[k & 3] : idxB[k & 3];

            float d = 0.f;
#pragma unroll
            for (int j = 0; j < 5; j++) {
                float4 sq = g_probs[j * N_POINTS + pt];
                float4 qq = g_probs[j * N_POINTS + nb];
                float d0 = sq.x - qq.x;
                float d1 = sq.y - qq.y;
                float d2 = sq.z - qq.z;
                float d3 = sq.w - qq.w;
                d = fmaf(d0, d0, d); d = fmaf(d1, d1, d);
                d = fmaf(d2, d2, d); d = fmaf(d3, d3, d);
            }
            acc += d;
            cnt++;
        }
    }

    // block reduction (32 warps) -> one atomic per block -> last-block finalize
#pragma unroll
    for (int o = 16; o > 0; o >>= 1) {
        acc += __shfl_down_sync(FULLMASK, acc, o);
        cnt += __shfl_down_sync(FULLMASK, cnt, o);
    }
    __shared__ float ssum[32];
    __shared__ int   scnt[32];
    int lane = threadIdx.x & 31;
    int w    = threadIdx.x >> 5;
    if (lane == 0) { ssum[w] = acc; scnt[w] = cnt; }
    __syncthreads();
    if (w == 0) {
        int nw = TPB2 >> 5;
        acc = (lane < nw) ? ssum[lane] : 0.f;
        cnt = (lane < nw) ? scnt[lane] : 0;
#pragma unroll
        for (int o = 16; o > 0; o >>= 1) {
            acc += __shfl_down_sync(FULLMASK, acc, o);
            cnt += __shfl_down_sync(FULLMASK, cnt, o);
        }
        if (lane == 0) {
            atomicAdd(&g_sum, (double)acc);
            atomicAdd(&g_count, (unsigned long long)cnt);
            __threadfence();
            unsigned int done = atomicAdd(&g_done, 1u);
            if (done == gridDim.x - 1) {
                double sum = *(volatile double*)&g_sum;
                double c   = (double)*(volatile unsigned long long*)&g_count;
                if (c < 1.0) c = 1.0;
                out[0] = (float)(sum / c);
                g_done = 0;   // self-reset for next graph replay
            }
        }
    }
}

extern "C" void kernel_launch(void* const* d_in, const int* in_sizes, int n_in,
                              void* d_out, int out_size) {
    const float* seg_logits = (const float*)d_in[0];
    // d_in[1] = coord, unused
    const void* labels = d_in[2];
    const void* ref    = d_in[3];
    float* out = (float*)d_out;

    cudaFuncSetAttribute(lac_pass2, cudaFuncAttributeMaxDynamicSharedMemorySize,
                         SMEM_BYTES);

    const int TPB1 = 256;
    const int blocks1 = (N_POINTS + TPB1 - 1) / TPB1;   // 1024

    lac_pass1<<<blocks1, TPB1>>>(seg_logits, labels, ref);
    lac_pass2<<<GRID2, TPB2, SMEM_BYTES>>>(ref, out);
}